// round 15
// baseline (speedup 1.0000x reference)
#include <cuda_runtime.h>

// Problem constants (fixed by the reference).
#define BB 320          // batch
#define CC 80           // label dim
#define DD 128          // feature dim
#define NA 30           // num anchors == num blocks
#define NT 320          // threads per block (10 warps); NT == BB
#define WREG 288        // staging floats per warp (1152 B)

// Cross-block combine scratch (no allocations allowed).
__device__ float g_bsum[NA];
__device__ int   g_bcnt[NA];
__device__ unsigned g_done = 0;   // ticket; last block resets -> replay safe

__device__ __forceinline__ float dot4(float4 a, float4 b) {
    return a.x * b.x + a.y * b.y + a.z * b.z + a.w * b.w;
}

extern __shared__ __align__(16) float dyn[];   // 10 * WREG floats

__global__ void __launch_bounds__(NT)
triplet_v4(const int* __restrict__ label,
           const float* __restrict__ src,
           const float* __restrict__ tgt,
           float* __restrict__ out) {
    const int t = threadIdx.x;
    const int w = t >> 5;         // 0..9
    const int lane = t & 31;
    const int b = blockIdx.x;     // this block owns the rank-b anchor

    __shared__ __align__(16) float s_u[DD];      // u = sum_c t_c / ||t_c||
    __shared__ __align__(16) float s_srcA[DD];   // anchor source row
    __shared__ __align__(16) float s_div[BB];    // diversity per row
    __shared__ float s_nt[BB];                   // ||t_c||
    __shared__ float s_ns[BB];                   // ||s_j||
    __shared__ float s_sn[BB];                   // sqrt(label popcount)
    __shared__ unsigned s_lp[BB][3];             // packed labels
    __shared__ float s_fd[BB];                   // fd[a, c]
    __shared__ unsigned char s_mask[BB];         // 1 = pos, 2 = neg
    __shared__ float s_posfd[BB];                // compacted positive fds
    __shared__ float s_rf[10];
    __shared__ int s_ri[10];
    __shared__ int s_npos;
    __shared__ int s_anchor;
    __shared__ int s_last;

    float* preg = dyn + w * WREG;                // this warp's staging tile

    const float4* tgt4 = reinterpret_cast<const float4*>(tgt);
    const float4* src4 = reinterpret_cast<const float4*>(src);

    // ===== Stage: ONE memory round-trip for tgt + src + labels =============
    // Warps 0-4: tgt cols (norms + later u). Warps 5-9: src rows (norms).
    // Every warp also packs 32 label rows, interleaved into the same bursts.
    {
        const bool isT = (w < 5);
        const float4* base4 = isT ? tgt4 : src4;
        const int RC0 = isT ? (w * 64) : ((w - 5) * 64);
        float* outn = isT ? s_nt : s_ns;
        const int Lr0 = w * 32;

#pragma unroll
        for (int p = 0; p < 8; p++) {
            // 8 independent float4 LDGs into registers (forces batching)
            float4 vv[8];
#pragma unroll
            for (int i = 0; i < 8; i++)
                vv[i] = base4[(RC0 + p * 8 + i) * (DD / 4) + lane];
            // 12 independent label LDGs (4 rows) batched with the burst
            int l0[4], l1[4], l2[4];
#pragma unroll
            for (int j = 0; j < 4; j++) {
                const int r = Lr0 + p * 4 + j;
                l0[j] = label[r * CC + lane];
                l1[j] = label[r * CC + 32 + lane];
                l2[j] = (lane < 16) ? label[r * CC + 64 + lane] : 0;
            }
            // square-dots to staging (stride 34)
#pragma unroll
            for (int i = 0; i < 8; i++)
                preg[i * 34 + lane] = dot4(vv[i], vv[i]);
            // pack labels via ballot
#pragma unroll
            for (int j = 0; j < 4; j++) {
                const int r = Lr0 + p * 4 + j;
                unsigned b0 = __ballot_sync(~0u, l0[j] != 0);
                unsigned b1 = __ballot_sync(~0u, l1[j] != 0);
                unsigned b2 = __ballot_sync(~0u, (lane < 16) && (l2[j] != 0));
                if (lane == 0) {
                    s_lp[r][0] = b0; s_lp[r][1] = b1; s_lp[r][2] = b2;
                    s_sn[r] = sqrtf((float)(__popc(b0) + __popc(b1) + __popc(b2)));
                }
            }
            __syncwarp();
            // transpose-reduce 8 rows x 32 chunks -> norms
            {
                const int row = lane & 7;
                const int off = (lane >> 3) * 8;
                const float* pr = preg + row * 34 + off;
                float s = 0.f;
#pragma unroll
                for (int l = 0; l < 8; l++) s += pr[l];
                s += __shfl_xor_sync(~0u, s, 8);
                s += __shfl_xor_sync(~0u, s, 16);
                if (lane < 8) outn[RC0 + p * 8 + row] = sqrtf(s);
            }
            __syncwarp();
        }

        // T-warps: u partial over their 64 cols (L1-hot re-read, no reduction)
        if (isT) {
            float ux = 0.f, uy = 0.f, uz = 0.f, uw = 0.f;
#pragma unroll 8
            for (int i = 0; i < 64; i++) {
                float4 v = tgt4[(RC0 + i) * (DD / 4) + lane];
                float inv = 1.0f / s_nt[RC0 + i];
                ux += v.x * inv; uy += v.y * inv; uz += v.z * inv; uw += v.w * inv;
            }
            __syncwarp();
            reinterpret_cast<float4*>(preg)[lane] = make_float4(ux, uy, uz, uw);
        }
    }
    __syncthreads();
    if (t < DD) {                                  // fixed-order 5-way combine
        float s = 0.f;
#pragma unroll
        for (int ww = 0; ww < 5; ww++) s += dyn[ww * WREG + t];
        s_u[t] = s;
    }
    __syncthreads();

    // ===== du pass: div[j] = 1 - (s_j . u) / (||s_j|| * 320) ===============
    // [factorization validated exact: rel_err 0.0 in R6/R11]
    {
        const int r0 = w * 32;
        const float4 uu = reinterpret_cast<const float4*>(s_u)[lane];
#pragma unroll
        for (int p = 0; p < 4; p++) {
#pragma unroll 8
            for (int i = 0; i < 8; i++) {
                float4 v = src4[(r0 + p * 8 + i) * (DD / 4) + lane];
                preg[i * 34 + lane] = dot4(v, uu);
            }
            __syncwarp();
            {
                const int row = lane & 7;
                const int off = (lane >> 3) * 8;
                const float* pr = preg + row * 34 + off;
                float du = 0.f;
#pragma unroll
                for (int l = 0; l < 8; l++) du += pr[l];
                du += __shfl_xor_sync(~0u, du, 8);
                du += __shfl_xor_sync(~0u, du, 16);
                if (lane < 8) {
                    const int r = r0 + p * 8 + row;
                    s_div[r] = 1.0f - du / (s_ns[r] * 320.0f);
                }
            }
            __syncwarp();
        }
    }
    __syncthreads();

    // ===== Rank (top_k tie-break -> permutation); take rank == b ===========
    {
        const float da = s_div[t];
        const float4* dv4 = reinterpret_cast<const float4*>(s_div);
        int cgt = 0;
#pragma unroll 4
        for (int k4 = 0; k4 < BB / 4; k4++) {
            float4 d4 = dv4[k4];
            const int k = k4 * 4;
            cgt += (d4.x > da || (d4.x == da && (k + 0) < t)) ? 1 : 0;
            cgt += (d4.y > da || (d4.y == da && (k + 1) < t)) ? 1 : 0;
            cgt += (d4.z > da || (d4.z == da && (k + 2) < t)) ? 1 : 0;
            cgt += (d4.w > da || (d4.w == da && (k + 3) < t)) ? 1 : 0;
        }
        if (cgt == b) s_anchor = t;               // exactly one writer
    }
    __syncthreads();
    const int a = s_anchor;

    if (w == 0)
        reinterpret_cast<float4*>(s_srcA)[lane] = src4[a * (DD / 4) + lane];
    __syncthreads();

    // ===== fd[a,c] + pos/neg mask (transpose reduction, tgt L1/L2-hot) =====
    {
        const int c0 = w * 32;
        const float4 sa = reinterpret_cast<const float4*>(s_srcA)[lane];
        const unsigned la0 = s_lp[a][0], la1 = s_lp[a][1], la2 = s_lp[a][2];
        const float sna = s_sn[a], nsa = s_ns[a];
#pragma unroll
        for (int p = 0; p < 4; p++) {
#pragma unroll 8
            for (int i = 0; i < 8; i++) {
                float4 v = tgt4[(c0 + p * 8 + i) * (DD / 4) + lane];
                preg[i * 34 + lane] = dot4(v, sa);
            }
            __syncwarp();
            {
                const int row = lane & 7;
                const int off = (lane >> 3) * 8;
                const float* pr = preg + row * 34 + off;
                float d = 0.f;
#pragma unroll
                for (int l = 0; l < 8; l++) d += pr[l];
                d += __shfl_xor_sync(~0u, d, 8);
                d += __shfl_xor_sync(~0u, d, 16);
                if (lane < 8) {
                    const int c = c0 + p * 8 + row;
                    float sim = d / fmaxf(nsa * s_nt[c], 1e-8f);
                    s_fd[c] = fmaxf(0.f, 1.f - sim);
                    int dl = __popc(la0 & s_lp[c][0]) + __popc(la1 & s_lp[c][1]) +
                             __popc(la2 & s_lp[c][2]);
                    float ldv = 1.f - fminf(1.f, (float)dl / (sna * s_sn[c]));
                    unsigned char m = 0;
                    if (ldv >= 0.5f) m = 2;                    // negative
                    else if (ldv <= 0.2f && c != a) m = 1;     // positive
                    s_mask[c] = m;
                }
            }
            __syncwarp();
        }
    }
    __syncthreads();

    // ===== Deterministic positive compaction (warp 0) ======================
    // pos/neg disjoint (gamma < beta) => p != n and a != n are automatic.
    int np;
    if (w == 0) {
        int acc = 0;
#pragma unroll
        for (int j0 = 0; j0 < BB; j0 += 32) {
            bool p = (s_mask[j0 + lane] == 1);
            unsigned bal = __ballot_sync(~0u, p);
            if (p) s_posfd[acc + __popc(bal & ((1u << lane) - 1u))] = s_fd[j0 + lane];
            acc += __popc(bal);
        }
        if (lane == 0) s_npos = acc;
    }
    __syncthreads();
    np = s_npos;

    // ===== Pair sum (thread t owns column t) ===============================
    float lsum = 0.f;
    int lnn = 0;
    if (s_mask[t] == 2) {
        lnn = 1;
        const float fn = s_fd[t];
        for (int p = 0; p < np; p++)
            lsum += fmaxf(0.f, (s_posfd[p] - fn) + 0.5f);
    }
#pragma unroll
    for (int o = 16; o > 0; o >>= 1) {
        lsum += __shfl_xor_sync(~0u, lsum, o);
        lnn += __shfl_xor_sync(~0u, lnn, o);
    }
    if (lane == 0) { s_rf[w] = lsum; s_ri[w] = lnn; }
    __syncthreads();

    // ===== Finalize: last-block ticket, fixed-order 30-way combine =========
    if (t == 0) {
        float ts = 0.f; int tn = 0;
#pragma unroll
        for (int ww = 0; ww < 10; ww++) { ts += s_rf[ww]; tn += s_ri[ww]; }
        g_bsum[b] = ts;
        g_bcnt[b] = np * tn;
        __threadfence();
        unsigned tk = atomicAdd(&g_done, 1u);
        s_last = (tk == (unsigned)(NA - 1)) ? 1 : 0;
    }
    __syncthreads();

    if (s_last) {
        if (t == 0) g_done = 0;          // reset for next graph replay
        __threadfence();                 // acquire other blocks' partials
        if (w == 0) {
            float ps = (lane < NA) ? g_bsum[lane] : 0.f;
            int pc = (lane < NA) ? g_bcnt[lane] : 0;
#pragma unroll
            for (int o = 16; o > 0; o >>= 1) {
                ps += __shfl_xor_sync(~0u, ps, o);
                pc += __shfl_xor_sync(~0u, pc, o);
            }
            if (lane == 0) out[0] = ps / ((float)pc + 1e-4f);
        }
    }
}

extern "C" void kernel_launch(void* const* d_in, const int* in_sizes, int n_in,
                              void* d_out, int out_size) {
    const int* label = (const int*)d_in[0];
    const float* src = (const float*)d_in[1];
    const float* tgt = (const float*)d_in[2];
    float* out = (float*)d_out;
    (void)in_sizes; (void)n_in; (void)out_size;

    triplet_v4<<<NA, NT, 10 * WREG * (int)sizeof(float)>>>(label, src, tgt, out);
}